// round 6
// baseline (speedup 1.0000x reference)
#include <cuda_runtime.h>

#define S_SRC 16384
#define T_GRID 4096
#define NHBR 8
#define BATCH 4
#define EDIM 16
#define GBINS 32
#define NBINS (GBINS * GBINS)
#define CELL (1.0f / 32.0f)
#define BCAP 96
#define FUSED_BLOCKS 128

// Scratch (static device globals — no allocation). g_cnt is zero-initialized
// at module load and re-zeroed at the end of every launch (in interp_kernel),
// so each replay of the graph sees zeroed counts. Barrier generation counter
// only ever increments (replay-safe); arrival count self-resets.
__device__ float  g_xg[BATCH * T_GRID * EDIM];
__device__ int    g_cnt[NBINS];
__device__ float2 g_bxy[NBINS * BCAP];
__device__ int    g_bidx[NBINS * BCAP];
__device__ int    g_bar_count = 0;
__device__ int    g_bar_gen = 0;

__device__ __forceinline__ int clampb(int v) { return min(max(v, 0), GBINS - 1); }

// Grid-wide barrier. Safe because the full grid is co-resident (128 blocks
// x 256 threads at this register count << SM capacity). Generation-based:
// reading a stale generation is impossible before this block arrives, and
// seeing a bumped generation means the barrier already completed.
__device__ __forceinline__ void grid_barrier() {
  __syncthreads();
  if (threadIdx.x == 0) {
    __threadfence();
    const int gen = atomicAdd(&g_bar_gen, 0);
    if (atomicAdd(&g_bar_count, 1) == FUSED_BLOCKS - 1) {
      atomicExch(&g_bar_count, 0);
      __threadfence();
      atomicAdd(&g_bar_gen, 1);
    } else {
      while (atomicAdd(&g_bar_gen, 0) == gen) {
      }
    }
    __threadfence();
  }
  __syncthreads();
}

// ---------------------------------------------------------------------------
// kNN helpers. Key = (f32bits(d2)<<32)|idx reproduces lax.top_k(-d2) order
// including tie-break by lower index.
// ---------------------------------------------------------------------------
__device__ __forceinline__ void scan_bin8(int b, int l, float gx, float gy,
                                          unsigned long long best[8],
                                          float& worst) {
  const int s = b * BCAP;
  const int e = s + min(g_cnt[b], BCAP);
  for (int j = s + l; j < e; j += 8) {
    const float2 p = g_bxy[j];
    const float dx = gx - p.x;
    const float dy = gy - p.y;
    const float d2 = fmaf(dy, dy, dx * dx);
    if (d2 <= worst) {
      unsigned long long key =
          ((unsigned long long)__float_as_uint(d2) << 32) | (unsigned)g_bidx[j];
      if (key < best[7]) {
        best[7] = key;
#pragma unroll
        for (int k = 7; k > 0; k--) {
          unsigned long long lo = (best[k] < best[k - 1]) ? best[k] : best[k - 1];
          unsigned long long hi = (best[k] < best[k - 1]) ? best[k - 1] : best[k];
          best[k - 1] = lo;
          best[k] = hi;
        }
        worst = __uint_as_float((unsigned)(best[7] >> 32));
      }
    }
  }
}

__device__ __forceinline__ unsigned long long merge8(
    const unsigned long long best[8], int l, unsigned gmask,
    unsigned long long& mine) {
  unsigned long long cand = best[0];
  int p = 0;
  unsigned long long m = 0;
#pragma unroll
  for (int k = 0; k < 8; k++) {
    m = cand;
#pragma unroll
    for (int off = 4; off > 0; off >>= 1) {
      unsigned long long o = __shfl_xor_sync(gmask, m, off, 8);
      m = (o < m) ? o : m;
    }
    if (l == k) mine = m;
    if (cand == m) {
      p++;
      cand = (p < 8) ? best[p] : 0xFFFFFFFFFFFFFFFFULL;
    }
  }
  return m;
}

__device__ __forceinline__ void fma4(float4& a, float w, const float4 v) {
  a.x = fmaf(w, v.x, a.x);
  a.y = fmaf(w, v.y, a.y);
  a.z = fmaf(w, v.z, a.z);
  a.w = fmaf(w, v.w, a.w);
}

// ---------------------------------------------------------------------------
// Fused kernel: bin build -> grid barrier -> exact kNN (8 lanes/point) ->
// PE MLP -> LN -> logits -> softmax -> xg gather.
// Block = 256 threads = 32 grid points. Grid MUST be FUSED_BLOCKS.
// ---------------------------------------------------------------------------
__global__ __launch_bounds__(256) void fused_kernel(
    const float* __restrict__ x,
    const float* __restrict__ cs, const float* __restrict__ cg,
    const float* __restrict__ w1, const float* __restrict__ b1,
    const float* __restrict__ w2, const float* __restrict__ b2,
    const float* __restrict__ lng, const float* __restrict__ lnb,
    const float* __restrict__ kw, const float* __restrict__ kb) {
  __shared__ float sW1[128];
  __shared__ float sB1[64];
  __shared__ float4 sW2[512];
  __shared__ float sB2[32], sLNG[32], sLNB[32], sKB[8];
  __shared__ float4 sKW[512];
  __shared__ float sPL[32 * 64];
  __shared__ int sIDX[256];
  __shared__ float sWgt[256];

  const int tid = threadIdx.x;
  const int gid = blockIdx.x * 256 + tid;

  // Weight-table prefetch (overlaps bin build + knn).
  if (tid < 128) sW1[tid] = w1[tid];
  if (tid < 64) sB1[tid] = b1[tid];
  for (int i = tid; i < 512; i += 256) sW2[i] = ((const float4*)w2)[i];
  for (int i = tid; i < 512; i += 256) sKW[i] = ((const float4*)kw)[i];
  if (tid < 32) {
    sB2[tid] = b2[tid];
    sLNG[tid] = lng[tid];
    sLNB[tid] = lnb[tid];
  }
  if (tid < 8) sKB[tid] = kb[tid];

  // ---- Phase 0: bin build (first 16384 threads; g_cnt pre-zeroed) ----
  if (gid < S_SRC) {
    const float px = cs[gid];
    const float py = cs[S_SRC + gid];
    const int b = clampb((int)(px * (float)GBINS)) * GBINS +
                  clampb((int)(py * (float)GBINS));
    const int p = atomicAdd(&g_cnt[b], 1);
    if (p < BCAP) {
      g_bxy[b * BCAP + p] = make_float2(px, py);
      g_bidx[b * BCAP + p] = gid;
    }
  }
  grid_barrier();

  // ---- Phase 1: kNN ----
  const int t = blockIdx.x * 32 + (tid >> 3);
  const int l = tid & 7;
  const unsigned gmask = 0xFFu << ((tid & 31) & 24);
  const float gx = cg[t];
  const float gy = cg[T_GRID + t];
  const int hbx = clampb((int)(gx * (float)GBINS));
  const int hby = clampb((int)(gy * (float)GBINS));

  unsigned long long best[8];
#pragma unroll
  for (int i = 0; i < 8; i++) best[i] = 0x7F800000FFFFFFFFULL;
  float worst = __int_as_float(0x7F800000);

  {
    const int x0 = max(hbx - 1, 0), x1 = min(hbx + 1, GBINS - 1);
    const int y0 = max(hby - 1, 0), y1 = min(hby + 1, GBINS - 1);
    for (int bx = x0; bx <= x1; bx++)
      for (int by = y0; by <= y1; by++)
        scan_bin8(bx * GBINS + by, l, gx, gy, best, worst);
  }

  unsigned long long mine;
  unsigned long long m8 = merge8(best, l, gmask, mine);
  float gw = __uint_as_float((unsigned)(m8 >> 32));

  for (int r = 2; r < GBINS; r++) {
    const float dmin = (float)(r - 1) * CELL;
    if (dmin * dmin > gw) break;
    const int x0 = max(hbx - r, 0), x1 = min(hbx + r, GBINS - 1);
    for (int bx = x0; bx <= x1; bx++) {
      if (abs(bx - hbx) == r) {
        const int y0 = max(hby - r, 0), y1 = min(hby + r, GBINS - 1);
        for (int by = y0; by <= y1; by++)
          scan_bin8(bx * GBINS + by, l, gx, gy, best, worst);
      } else {
        if (hby - r >= 0) scan_bin8(bx * GBINS + hby - r, l, gx, gy, best, worst);
        if (hby + r <= GBINS - 1)
          scan_bin8(bx * GBINS + hby + r, l, gx, gy, best, worst);
      }
    }
    m8 = merge8(best, l, gmask, mine);
    gw = __uint_as_float((unsigned)(m8 >> 32));
  }

  const int si = (int)(mine & 0xFFFFFFFFu);
  sIDX[tid] = si;

  // ---- Phase 2: PE MLP -> LN -> partial logits ----
  const float r0 = cs[si] - gx;
  const float r1 = cs[S_SRC + si] - gy;
  const int n = tid & 7;

  __syncthreads();  // weight tables ready (already are, post-barrier)

  float pe[32];
#pragma unroll
  for (int d = 0; d < 32; d++) pe[d] = sB2[d];

#pragma unroll 2
  for (int j = 0; j < 64; j++) {
    float h = fmaf(r1, sW1[64 + j], fmaf(r0, sW1[j], sB1[j]));
    float z = 0.7978845608028654f * fmaf(0.044715f, h * h * h, h);
    float g = h * __fdividef(1.0f, 1.0f + __expf(-2.0f * z));  // gelu_tanh
#pragma unroll
    for (int q = 0; q < 8; q++) {
      float4 wv = sW2[j * 8 + q];
      pe[q * 4 + 0] = fmaf(g, wv.x, pe[q * 4 + 0]);
      pe[q * 4 + 1] = fmaf(g, wv.y, pe[q * 4 + 1]);
      pe[q * 4 + 2] = fmaf(g, wv.z, pe[q * 4 + 2]);
      pe[q * 4 + 3] = fmaf(g, wv.w, pe[q * 4 + 3]);
    }
  }

  float mu = 0.f;
#pragma unroll
  for (int d = 0; d < 32; d++) mu += pe[d];
  mu *= (1.0f / 32.0f);
  float var = 0.f;
#pragma unroll
  for (int d = 0; d < 32; d++) {
    float c = pe[d] - mu;
    var = fmaf(c, c, var);
  }
  var *= (1.0f / 32.0f);
  const float rstd = rsqrtf(var + 1e-5f);

  float pl[8];
#pragma unroll
  for (int q = 0; q < 8; q++) pl[q] = 0.f;
#pragma unroll 4
  for (int d = 0; d < 32; d++) {
    float kf = fmaf((pe[d] - mu) * rstd, sLNG[d], sLNB[d]);
    float4 a = sKW[(n * 32 + d) * 2 + 0];
    float4 bq = sKW[(n * 32 + d) * 2 + 1];
    pl[0] = fmaf(kf, a.x, pl[0]);
    pl[1] = fmaf(kf, a.y, pl[1]);
    pl[2] = fmaf(kf, a.z, pl[2]);
    pl[3] = fmaf(kf, a.w, pl[3]);
    pl[4] = fmaf(kf, bq.x, pl[4]);
    pl[5] = fmaf(kf, bq.y, pl[5]);
    pl[6] = fmaf(kf, bq.z, pl[6]);
    pl[7] = fmaf(kf, bq.w, pl[7]);
  }
  const int lt = tid >> 3;
#pragma unroll
  for (int q = 0; q < 8; q++) sPL[lt * 64 + n * 8 + q] = pl[q];
  __syncthreads();

  // ---- Phase 3: softmax over neighbors ----
  const int jj = tid & 7;
  float lg = sKB[jj];
#pragma unroll
  for (int n2 = 0; n2 < 8; n2++) lg += sPL[lt * 64 + n2 * 8 + jj];
  float mx = lg;
#pragma unroll
  for (int off = 4; off > 0; off >>= 1)
    mx = fmaxf(mx, __shfl_xor_sync(0xffffffffu, mx, off));
  float e = __expf(lg - mx);
  float ssum = e;
#pragma unroll
  for (int off = 4; off > 0; off >>= 1)
    ssum += __shfl_xor_sync(0xffffffffu, ssum, off);
  sWgt[lt * 8 + jj] = e / ssum;
  __syncthreads();

  // ---- Phase 4: xg gather. unit = (point, batch); 2 threads x 8 channels ----
  const int unit = tid >> 1;
  const int half = tid & 1;
  const int pt = unit >> 2;
  const int b = unit & 3;
  const int tg = blockIdx.x * 32 + pt;
  float4 a0 = {0, 0, 0, 0}, a1 = a0;
#pragma unroll
  for (int nn = 0; nn < NHBR; nn++) {
    const int s = sIDX[pt * 8 + nn];
    const float w = sWgt[pt * 8 + nn];
    const float4* xp =
        (const float4*)(x + (size_t)(b * S_SRC + s) * EDIM + half * 8);
    fma4(a0, w, xp[0]);
    fma4(a1, w, xp[1]);
  }
  float4* op = (float4*)(g_xg + (size_t)((b << 12) + tg) * EDIM + half * 8);
  op[0] = a0;
  op[1] = a1;
}

// ---------------------------------------------------------------------------
// Gaussian axis window, factorized: exp(-2(d-off_j)^2) = G*C_j*r^j with
// r = exp(-20d/89); G cancels in normalization (common path: 1 __expf).
// Edge-clipped cases (irp<=2 / irp>=62) corrected exactly.
// ---------------------------------------------------------------------------
__device__ __forceinline__ void axis_weights(float pos, float rp,
                                             const float* __restrict__ sC,
                                             float w[5]) {
  const float delta = rp - pos;  // in [-0.5, 0.5]
  const float lnr = -(20.0f / 89.0f) * delta;
  const float r = __expf(lnr);

  float S0 = 0.f, S1 = 0.f, S2 = 0.f, S3 = 0.f, S4 = 0.f;
  float rr = 1.0f;
#pragma unroll
  for (int k = 0; k < 18; k++) {
    S0 = fmaf(sC[k], rr, S0);
    S1 = fmaf(sC[18 + k], rr, S1);
    S2 = fmaf(sC[36 + k], rr, S2);
    S3 = fmaf(sC[54 + k], rr, S3);
    S4 = fmaf(sC[72 + k], rr, S4);
    rr *= r;
  }
  const float q = rr;  // r^18
  const float q2 = q * q;
  w[0] = S0;
  w[1] = q * S1;
  w[2] = q2 * S2;
  w[3] = q2 * q * S3;
  w[4] = q2 * q2 * S4;

  const int irp = (int)rp;
  if (irp <= 2 || irp >= 62) {
    const float G = __expf(fmaf(-2.0f * delta, delta, 10.0f * delta));
#pragma unroll
    for (int i = 0; i < 5; i++) w[i] *= G;
    if (irp <= 2) {
      const int j0 = (int)ceilf((2.5f - rp) * 17.8f);
      const float K = __expf(-2.0f * pos * pos);
      float rj = G;
#pragma unroll
      for (int i = 0; i < 5; i++) {
        const int jlo = i * 18;
        const int jhi = min(j0, jlo + 18);
        float c = 0.f;
        for (int j = jlo; j < jhi; j++) {
          c += K - sC[j] * rj;
          rj *= r;
        }
        w[i] += c;
      }
    } else {
      const float d64 = 64.0f - pos;
      const float K = __expf(-2.0f * d64 * d64);
      const int jc = (int)floorf((66.5f - rp) * 17.8f) + 1;
      float rjj = G * __expf(lnr * (float)jc);
#pragma unroll
      for (int i = 0; i < 5; i++) {
        const int jlo = max(jc, i * 18);
        const int jhi = (i + 1) * 18;
        float c = 0.f;
        for (int j = jlo; j < jhi; j++) {
          c += K - sC[j] * rjj;
          rjj *= r;
        }
        w[i] += c;
      }
    }
  }
}

// ---------------------------------------------------------------------------
// Gaussian-window resampling. FOUR threads per (b, n): each thread computes
// both axes' windows (cheap) and accumulates its own float4 of channels.
// Also zeroes g_cnt (block 0) for the next graph replay.
// ---------------------------------------------------------------------------
__global__ __launch_bounds__(512) void interp_kernel(
    const float* __restrict__ ct, float* __restrict__ out) {
  __shared__ float sC[90];
  {
    const int tt = threadIdx.x;
    if (tt < 90) {
      float off = fmaf((float)tt, -5.0f / 89.0f, 2.5f);
      sC[tt] = __expf(-2.0f * off * off);
    }
    if (blockIdx.x == 0) {
      for (int i = tt; i < NBINS; i += 512) g_cnt[i] = 0;
    }
  }
  __syncthreads();

  const int gid4 = blockIdx.x * 512 + threadIdx.x;  // 131072 = 4*B*N
  const int tgt = gid4 >> 2;
  const int quad = gid4 & 3;
  const int b = tgt >> 13;
  const float2 c2 = ((const float2*)ct)[tgt];
  const float posx = c2.y * 63.0f;
  const float posy = c2.x * 63.0f;
  const float rpx = rintf(posx);
  const float rpy = rintf(posy);

  float wx[5], wy[5];
  axis_weights(posx, rpx, sC, wx);
  axis_weights(posy, rpy, sC, wy);

  const float sx = wx[0] + wx[1] + wx[2] + wx[3] + wx[4];
  const float sy = wy[0] + wy[1] + wy[2] + wy[3] + wy[4];
  const float inv = 1.0f / (sx * sy);

  int ixi[5], iyi[5];
  const int irpx = (int)rpx;
  const int irpy = (int)rpy;
#pragma unroll
  for (int k = 0; k < 5; k++) {
    ixi[k] = min(max(irpx + 2 - k, 0), 63);
    iyi[k] = min(max(irpy + 2 - k, 0), 63);
  }

  float4 acc = {0, 0, 0, 0};
  const float* gbase = g_xg + (size_t)b * (T_GRID * EDIM) + quad * 4;
#pragma unroll
  for (int kx = 0; kx < 5; kx++) {
    const int rowbase = ixi[kx] << 6;
    const float wxk = wx[kx] * inv;
#pragma unroll
    for (int ky = 0; ky < 5; ky++) {
      const float wc = wxk * wy[ky];
      const float4 v =
          *(const float4*)(gbase + (size_t)(rowbase + iyi[ky]) * EDIM);
      fma4(acc, wc, v);
    }
  }
  ((float4*)(out + (size_t)tgt * EDIM))[quad] = acc;
}

// ---------------------------------------------------------------------------
extern "C" void kernel_launch(void* const* d_in, const int* in_sizes, int n_in,
                              void* d_out, int out_size) {
  const float* x   = (const float*)d_in[0];
  const float* cs  = (const float*)d_in[1];
  const float* cg  = (const float*)d_in[2];
  const float* ct  = (const float*)d_in[3];
  const float* w1  = (const float*)d_in[4];
  const float* b1  = (const float*)d_in[5];
  const float* w2  = (const float*)d_in[6];
  const float* b2  = (const float*)d_in[7];
  const float* lng = (const float*)d_in[8];
  const float* lnb = (const float*)d_in[9];
  const float* kw  = (const float*)d_in[10];
  const float* kb  = (const float*)d_in[11];
  float* out = (float*)d_out;

  fused_kernel<<<FUSED_BLOCKS, 256>>>(x, cs, cg, w1, b1, w2, b2, lng, lnb, kw, kb);
  interp_kernel<<<256, 512>>>(ct, out);
}

// round 7
// speedup vs baseline: 1.0868x; 1.0868x over previous
#include <cuda_runtime.h>

#define S_SRC 16384
#define T_GRID 4096
#define NHBR 8
#define BATCH 4
#define EDIM 16
#define GBINS 32
#define NBINS (GBINS * GBINS)
#define CELL (1.0f / 32.0f)
#define BCAP 96

// Scratch (static device globals — no allocation). g_cnt zero-initialized at
// load; re-zeroed each launch by interp_kernel block 0 for graph replays.
__device__ int    g_idx[T_GRID * NHBR];
__device__ float  g_xg[BATCH * T_GRID * EDIM];
__device__ int    g_cnt[NBINS];
__device__ float2 g_bxy[NBINS * BCAP];
__device__ int    g_bidx[NBINS * BCAP];

__device__ __forceinline__ int clampb(int v) { return min(max(v, 0), GBINS - 1); }

// ---------------------------------------------------------------------------
// Binning: direct scatter into fixed-capacity bins (Poisson(16); BCAP=96
// cannot overflow in practice). Bin-internal order nondeterministic, but
// top-k uses a total order on (d2,idx) keys -> deterministic output.
// ---------------------------------------------------------------------------
__global__ __launch_bounds__(256) void bins_build(const float* __restrict__ cs) {
  const int i = blockIdx.x * 256 + threadIdx.x;
  const float x = cs[i];
  const float y = cs[S_SRC + i];
  const int b = clampb((int)(x * (float)GBINS)) * GBINS +
                clampb((int)(y * (float)GBINS));
  const int p = atomicAdd(&g_cnt[b], 1);
  if (p < BCAP) {
    g_bxy[b * BCAP + p] = make_float2(x, y);
    g_bidx[b * BCAP + p] = i;
  }
}

// ---------------------------------------------------------------------------
// Exact kNN (k=8): ONE WARP per grid point. Warp-uniform bin sweep (no
// intra-warp divergence), lane-local sorted top-8, 32-lane extraction merge.
// Key = (f32bits(d2)<<32)|idx reproduces lax.top_k(-d2) order + tie-break.
// ---------------------------------------------------------------------------
__device__ __forceinline__ void insert_key(unsigned long long key,
                                           unsigned long long best[8],
                                           float& worst) {
  if (key < best[7]) {
    best[7] = key;
#pragma unroll
    for (int k = 7; k > 0; k--) {
      unsigned long long lo = (best[k] < best[k - 1]) ? best[k] : best[k - 1];
      unsigned long long hi = (best[k] < best[k - 1]) ? best[k - 1] : best[k];
      best[k - 1] = lo;
      best[k] = hi;
    }
    worst = __uint_as_float((unsigned)(best[7] >> 32));
  }
}

__device__ __forceinline__ void try_candidate(int slot, float gx, float gy,
                                              unsigned long long best[8],
                                              float& worst) {
  const float2 p = g_bxy[slot];
  const float dx = gx - p.x;
  const float dy = gy - p.y;
  const float d2 = fmaf(dy, dy, dx * dx);
  if (d2 <= worst) {
    unsigned long long key =
        ((unsigned long long)__float_as_uint(d2) << 32) | (unsigned)g_bidx[slot];
    insert_key(key, best, worst);
  }
}

// 32-lane extraction merge: lane k (k<8) receives the k-th smallest across
// all lanes' sorted best[] lists in `mine`; returns the 8th smallest.
__device__ __forceinline__ unsigned long long merge8_32(
    const unsigned long long best[8], int lane, unsigned long long& mine) {
  unsigned long long cand = best[0];
  int p = 0;
  unsigned long long m = 0;
#pragma unroll
  for (int k = 0; k < 8; k++) {
    m = cand;
#pragma unroll
    for (int off = 16; off > 0; off >>= 1) {
      unsigned long long o = __shfl_xor_sync(0xffffffffu, m, off);
      m = (o < m) ? o : m;
    }
    if (lane == k) mine = m;
    if (cand == m) {  // unique keys (idx unique) -> exactly one owner advances
      p++;
      cand = (p < 8) ? best[p] : 0xFFFFFFFFFFFFFFFFULL;
    }
  }
  return m;
}

__global__ __launch_bounds__(256) void knn_kernel(const float* __restrict__ cg) {
  const int t = (blockIdx.x * 256 + threadIdx.x) >> 5;  // warp id = grid point
  const int lane = threadIdx.x & 31;

  const float gx = cg[t];
  const float gy = cg[T_GRID + t];
  const int hbx = clampb((int)(gx * (float)GBINS));
  const int hby = clampb((int)(gy * (float)GBINS));

  unsigned long long best[8];
#pragma unroll
  for (int i = 0; i < 8; i++) best[i] = 0x7F800000FFFFFFFFULL;
  float worst = __int_as_float(0x7F800000);

  // Lanes 0..8 preload the 3x3 neighborhood descriptors.
  int myCnt = 0, myBase = 0;
  if (lane < 9) {
    const int bx = hbx + (lane % 3) - 1;
    const int by = hby + (lane / 3) - 1;
    if (bx >= 0 && bx < GBINS && by >= 0 && by < GBINS) {
      const int b = bx * GBINS + by;
      myCnt = min(g_cnt[b], BCAP);
      myBase = b * BCAP;
    }
  }

  // Warp-uniform sweep: bin i candidates spread across lanes.
#pragma unroll
  for (int i = 0; i < 9; i++) {
    const int cnt = __shfl_sync(0xffffffffu, myCnt, i);
    const int base = __shfl_sync(0xffffffffu, myBase, i);
    for (int c = lane; c < cnt; c += 32)  // cnt~16 -> single round typical
      try_candidate(base + c, gx, gy, best, worst);
  }

  unsigned long long mine = 0;
  unsigned long long m8 = merge8_32(best, lane, mine);
  float gw = __uint_as_float((unsigned)(m8 >> 32));

  // Rare ring expansion (edge-of-domain sparsity). Warp-cooperative: each
  // lane owns ring cells lane, lane+32, ... and scans them serially.
  for (int r = 2; r < GBINS; r++) {
    const float dmin = (float)(r - 1) * CELL;
    if (dmin * dmin > gw) break;
    const int nring = 8 * r;
    for (int idx = lane; idx < nring; idx += 32) {
      const int seg = idx / (2 * r);
      const int off = idx - seg * 2 * r;
      int dx, dy;
      if (seg == 0) { dx = -r + off; dy = -r; }
      else if (seg == 1) { dx = -r + 1 + off; dy = r; }
      else if (seg == 2) { dx = -r; dy = -r + 1 + off; }
      else { dx = r; dy = -r + off; }
      const int bx = hbx + dx, by = hby + dy;
      if (bx < 0 || bx >= GBINS || by < 0 || by >= GBINS) continue;
      const int b = bx * GBINS + by;
      const int cnt = min(g_cnt[b], BCAP);
      const int base = b * BCAP;
      for (int c = 0; c < cnt; c++) try_candidate(base + c, gx, gy, best, worst);
    }
    m8 = merge8_32(best, lane, mine);
    gw = __uint_as_float((unsigned)(m8 >> 32));
  }

  if (lane < 8) g_idx[t * NHBR + lane] = (int)(mine & 0xFFFFFFFFu);
}

// ---------------------------------------------------------------------------
// Weights + xg: PE MLP (gelu via sigmoid) -> LN -> logits -> softmax ->
// xg gather. Block = 256 threads = 32 grid points.
// ---------------------------------------------------------------------------
__device__ __forceinline__ void fma4(float4& a, float w, const float4 v) {
  a.x = fmaf(w, v.x, a.x);
  a.y = fmaf(w, v.y, a.y);
  a.z = fmaf(w, v.z, a.z);
  a.w = fmaf(w, v.w, a.w);
}

__global__ __launch_bounds__(256) void weights_xg_kernel(
    const float* __restrict__ x,
    const float* __restrict__ cs, const float* __restrict__ cg,
    const float* __restrict__ w1, const float* __restrict__ b1,
    const float* __restrict__ w2, const float* __restrict__ b2,
    const float* __restrict__ lng, const float* __restrict__ lnb,
    const float* __restrict__ kw, const float* __restrict__ kb) {
  __shared__ float sW1[128];
  __shared__ float sB1[64];
  __shared__ float4 sW2[512];
  __shared__ float sB2[32], sLNG[32], sLNB[32], sKB[8];
  __shared__ float4 sKW[512];
  __shared__ float sPL[32 * 64];
  __shared__ int sIDX[256];
  __shared__ float sWgt[256];

  const int tid = threadIdx.x;
  if (tid < 128) sW1[tid] = w1[tid];
  if (tid < 64) sB1[tid] = b1[tid];
  for (int i = tid; i < 512; i += 256) sW2[i] = ((const float4*)w2)[i];
  for (int i = tid; i < 512; i += 256) sKW[i] = ((const float4*)kw)[i];
  if (tid < 32) {
    sB2[tid] = b2[tid];
    sLNG[tid] = lng[tid];
    sLNB[tid] = lnb[tid];
  }
  if (tid < 8) sKB[tid] = kb[tid];

  const int gid = blockIdx.x * 256 + tid;
  const int t = gid >> 3;
  const int n = tid & 7;
  const int si = g_idx[gid];
  sIDX[tid] = si;
  const float r0 = cs[si] - cg[t];
  const float r1 = cs[S_SRC + si] - cg[T_GRID + t];

  __syncthreads();

  float pe[32];
#pragma unroll
  for (int d = 0; d < 32; d++) pe[d] = sB2[d];

#pragma unroll 2
  for (int j = 0; j < 64; j++) {
    float h = fmaf(r1, sW1[64 + j], fmaf(r0, sW1[j], sB1[j]));
    float z = 0.7978845608028654f * fmaf(0.044715f, h * h * h, h);
    float g = h * __fdividef(1.0f, 1.0f + __expf(-2.0f * z));  // gelu_tanh
#pragma unroll
    for (int q = 0; q < 8; q++) {
      float4 wv = sW2[j * 8 + q];
      pe[q * 4 + 0] = fmaf(g, wv.x, pe[q * 4 + 0]);
      pe[q * 4 + 1] = fmaf(g, wv.y, pe[q * 4 + 1]);
      pe[q * 4 + 2] = fmaf(g, wv.z, pe[q * 4 + 2]);
      pe[q * 4 + 3] = fmaf(g, wv.w, pe[q * 4 + 3]);
    }
  }

  float mu = 0.f;
#pragma unroll
  for (int d = 0; d < 32; d++) mu += pe[d];
  mu *= (1.0f / 32.0f);
  float var = 0.f;
#pragma unroll
  for (int d = 0; d < 32; d++) {
    float c = pe[d] - mu;
    var = fmaf(c, c, var);
  }
  var *= (1.0f / 32.0f);
  const float rstd = rsqrtf(var + 1e-5f);

  float pl[8];
#pragma unroll
  for (int q = 0; q < 8; q++) pl[q] = 0.f;
#pragma unroll 4
  for (int d = 0; d < 32; d++) {
    float kf = fmaf((pe[d] - mu) * rstd, sLNG[d], sLNB[d]);
    float4 a = sKW[(n * 32 + d) * 2 + 0];
    float4 bq = sKW[(n * 32 + d) * 2 + 1];
    pl[0] = fmaf(kf, a.x, pl[0]);
    pl[1] = fmaf(kf, a.y, pl[1]);
    pl[2] = fmaf(kf, a.z, pl[2]);
    pl[3] = fmaf(kf, a.w, pl[3]);
    pl[4] = fmaf(kf, bq.x, pl[4]);
    pl[5] = fmaf(kf, bq.y, pl[5]);
    pl[6] = fmaf(kf, bq.z, pl[6]);
    pl[7] = fmaf(kf, bq.w, pl[7]);
  }
  const int lt = tid >> 3;
#pragma unroll
  for (int q = 0; q < 8; q++) sPL[lt * 64 + n * 8 + q] = pl[q];
  __syncthreads();

  const int jj = tid & 7;
  float lg = sKB[jj];
#pragma unroll
  for (int n2 = 0; n2 < 8; n2++) lg += sPL[lt * 64 + n2 * 8 + jj];
  float mx = lg;
#pragma unroll
  for (int off = 4; off > 0; off >>= 1)
    mx = fmaxf(mx, __shfl_xor_sync(0xffffffffu, mx, off));
  float e = __expf(lg - mx);
  float ssum = e;
#pragma unroll
  for (int off = 4; off > 0; off >>= 1)
    ssum += __shfl_xor_sync(0xffffffffu, ssum, off);
  sWgt[lt * 8 + jj] = e / ssum;
  __syncthreads();

  // xg gather: unit = (point, batch); 2 threads x 8 channels.
  const int unit = tid >> 1;
  const int half = tid & 1;
  const int pt = unit >> 2;
  const int b = unit & 3;
  const int tg = blockIdx.x * 32 + pt;
  float4 a0 = {0, 0, 0, 0}, a1 = a0;
#pragma unroll
  for (int nn = 0; nn < NHBR; nn++) {
    const int s = sIDX[pt * 8 + nn];
    const float w = sWgt[pt * 8 + nn];
    const float4* xp =
        (const float4*)(x + (size_t)(b * S_SRC + s) * EDIM + half * 8);
    fma4(a0, w, xp[0]);
    fma4(a1, w, xp[1]);
  }
  float4* op = (float4*)(g_xg + (size_t)((b << 12) + tg) * EDIM + half * 8);
  op[0] = a0;
  op[1] = a1;
}

// ---------------------------------------------------------------------------
// Gaussian axis window, factorized: exp(-2(d-off_j)^2) = G*C_j*r^j with
// r = exp(-20d/89); G cancels in normalization (common path: 1 __expf).
// Edge-clipped cases (irp<=2 / irp>=62) corrected exactly.
// ---------------------------------------------------------------------------
__device__ __forceinline__ void axis_weights(float pos, float rp,
                                             const float* __restrict__ sC,
                                             float w[5]) {
  const float delta = rp - pos;  // in [-0.5, 0.5]
  const float lnr = -(20.0f / 89.0f) * delta;
  const float r = __expf(lnr);

  float S0 = 0.f, S1 = 0.f, S2 = 0.f, S3 = 0.f, S4 = 0.f;
  float rr = 1.0f;
#pragma unroll
  for (int k = 0; k < 18; k++) {
    S0 = fmaf(sC[k], rr, S0);
    S1 = fmaf(sC[18 + k], rr, S1);
    S2 = fmaf(sC[36 + k], rr, S2);
    S3 = fmaf(sC[54 + k], rr, S3);
    S4 = fmaf(sC[72 + k], rr, S4);
    rr *= r;
  }
  const float q = rr;  // r^18
  const float q2 = q * q;
  w[0] = S0;
  w[1] = q * S1;
  w[2] = q2 * S2;
  w[3] = q2 * q * S3;
  w[4] = q2 * q2 * S4;

  const int irp = (int)rp;
  if (irp <= 2 || irp >= 62) {
    const float G = __expf(fmaf(-2.0f * delta, delta, 10.0f * delta));
#pragma unroll
    for (int i = 0; i < 5; i++) w[i] *= G;
    if (irp <= 2) {
      const int j0 = (int)ceilf((2.5f - rp) * 17.8f);
      const float K = __expf(-2.0f * pos * pos);
      float rj = G;
#pragma unroll
      for (int i = 0; i < 5; i++) {
        const int jlo = i * 18;
        const int jhi = min(j0, jlo + 18);
        float c = 0.f;
        for (int j = jlo; j < jhi; j++) {
          c += K - sC[j] * rj;
          rj *= r;
        }
        w[i] += c;
      }
    } else {
      const float d64 = 64.0f - pos;
      const float K = __expf(-2.0f * d64 * d64);
      const int jc = (int)floorf((66.5f - rp) * 17.8f) + 1;
      float rjj = G * __expf(lnr * (float)jc);
#pragma unroll
      for (int i = 0; i < 5; i++) {
        const int jlo = max(jc, i * 18);
        const int jhi = (i + 1) * 18;
        float c = 0.f;
        for (int j = jlo; j < jhi; j++) {
          c += K - sC[j] * rjj;
          rjj *= r;
        }
        w[i] += c;
      }
    }
  }
}

// ---------------------------------------------------------------------------
// Gaussian-window resampling. FOUR threads per (b, n): thread computes ONE
// axis window (quad&1 selects axis), exchanges with its partner via shfl,
// then gathers its own float4 of channels. Register-capped for occupancy.
// Also zeroes g_cnt (block 0) for the next graph replay.
// ---------------------------------------------------------------------------
__global__ __launch_bounds__(256, 4) void interp_kernel(
    const float* __restrict__ ct, float* __restrict__ out) {
  __shared__ float sC[90];
  {
    const int tt = threadIdx.x;
    if (tt < 90) {
      float off = fmaf((float)tt, -5.0f / 89.0f, 2.5f);
      sC[tt] = __expf(-2.0f * off * off);
    }
    if (blockIdx.x == 0) {
      for (int i = tt; i < NBINS; i += 256) g_cnt[i] = 0;
    }
  }
  __syncthreads();

  const int gid4 = blockIdx.x * 256 + threadIdx.x;  // 131072 = 4*B*N
  const int tgt = gid4 >> 2;
  const int quad = gid4 & 3;
  const int half = quad & 1;
  const int b = tgt >> 13;
  const float2 c2 = ((const float2*)ct)[tgt];
  const float posx = c2.y * 63.0f;
  const float posy = c2.x * 63.0f;
  const float rpx = rintf(posx);
  const float rpy = rintf(posy);

  const float pos = half ? posy : posx;
  const float rp = half ? rpy : rpx;

  float w[5];
  axis_weights(pos, rp, sC, w);

  float o[5];
#pragma unroll
  for (int i = 0; i < 5; i++) o[i] = __shfl_xor_sync(0xffffffffu, w[i], 1);

  float wx[5], wy[5];
#pragma unroll
  for (int i = 0; i < 5; i++) {
    wx[i] = half ? o[i] : w[i];
    wy[i] = half ? w[i] : o[i];
  }
  const float sx = wx[0] + wx[1] + wx[2] + wx[3] + wx[4];
  const float sy = wy[0] + wy[1] + wy[2] + wy[3] + wy[4];
  const float inv = 1.0f / (sx * sy);

  int ixi[5], iyi[5];
  const int irpx = (int)rpx;
  const int irpy = (int)rpy;
#pragma unroll
  for (int k = 0; k < 5; k++) {
    ixi[k] = min(max(irpx + 2 - k, 0), 63);
    iyi[k] = min(max(irpy + 2 - k, 0), 63);
  }

  float4 acc = {0, 0, 0, 0};
  const float* gbase = g_xg + (size_t)b * (T_GRID * EDIM) + quad * 4;
#pragma unroll
  for (int kx = 0; kx < 5; kx++) {
    const int rowbase = ixi[kx] << 6;
    const float wxk = wx[kx] * inv;
#pragma unroll
    for (int ky = 0; ky < 5; ky++) {
      const float wc = wxk * wy[ky];
      const float4 v =
          *(const float4*)(gbase + (size_t)(rowbase + iyi[ky]) * EDIM);
      fma4(acc, wc, v);
    }
  }
  ((float4*)(out + (size_t)tgt * EDIM))[quad] = acc;
}

// ---------------------------------------------------------------------------
extern "C" void kernel_launch(void* const* d_in, const int* in_sizes, int n_in,
                              void* d_out, int out_size) {
  const float* x   = (const float*)d_in[0];
  const float* cs  = (const float*)d_in[1];
  const float* cg  = (const float*)d_in[2];
  const float* ct  = (const float*)d_in[3];
  const float* w1  = (const float*)d_in[4];
  const float* b1  = (const float*)d_in[5];
  const float* w2  = (const float*)d_in[6];
  const float* b2  = (const float*)d_in[7];
  const float* lng = (const float*)d_in[8];
  const float* lnb = (const float*)d_in[9];
  const float* kw  = (const float*)d_in[10];
  const float* kb  = (const float*)d_in[11];
  float* out = (float*)d_out;

  bins_build<<<64, 256>>>(cs);
  knn_kernel<<<512, 256>>>(cg);
  weights_xg_kernel<<<128, 256>>>(x, cs, cg, w1, b1, w2, b2, lng, lnb, kw, kb);
  interp_kernel<<<512, 256>>>(ct, out);
}